// round 1
// baseline (speedup 1.0000x reference)
#include <cuda_runtime.h>

// Problem constants
#define Bb   4
#define Nn   2048
#define Ll   12
#define Dd   128
#define LD_  (Ll*Dd)      // 1536
#define MT   (Bb*Nn)      // 8192

// Scratch (device globals; no allocation)
__device__ float g_buf0[MT * Dd];   // 4 MB
__device__ float g_buf1[MT * Dd];   // 4 MB
__device__ float g_agg [MT * Dd];   // 4 MB
__device__ float g_deg [Nn];        // 1/clip(rowsum,1)

// ---------------------------------------------------------------------------
// deg kernel: g_deg[row] = 1 / max(sum_j adj[row][j], 1)
// ---------------------------------------------------------------------------
__global__ void deg_kernel(const float* __restrict__ adj) {
    int row = blockIdx.x;
    const float* r = adj + (size_t)row * Nn;
    float s = 0.f;
    for (int i = threadIdx.x; i < Nn; i += blockDim.x) s += r[i];
    __shared__ float sm[8];
    #pragma unroll
    for (int o = 16; o > 0; o >>= 1) s += __shfl_down_sync(0xffffffffu, s, o);
    if ((threadIdx.x & 31) == 0) sm[threadIdx.x >> 5] = s;
    __syncthreads();
    if (threadIdx.x == 0) {
        float t = 0.f;
        #pragma unroll
        for (int i = 0; i < 8; i++) t += sm[i];
        g_deg[row] = 1.0f / fmaxf(t, 1.0f);
    }
}

// ---------------------------------------------------------------------------
// Generic tiled fp32 GEMM: C = epi( A@Bm [+ A2@B2] )
//   BM=BN=64, BK=16, 256 threads, 4x4 per-thread microtile.
//   DUAL:      concatenated-K second GEMM (A2@B2), K2 == K required.
//   RELU:      epilogue relu
//   ROWSCALE:  multiply output row m by g_deg[m]   (requires M == Nn)
//   BIAS:      add bias[col]
// All of M%64, N%64, K%16 must hold (true for every call here).
// ---------------------------------------------------------------------------
template<bool DUAL, bool RELU, bool ROWSCALE, bool BIAS>
__global__ void __launch_bounds__(256)
gemm_k(const float* __restrict__ A,  const float* __restrict__ Bm,
       const float* __restrict__ A2, const float* __restrict__ B2,
       const float* __restrict__ bias,
       float* __restrict__ C,
       int M, int N, int K,
       size_t sA, size_t sB, size_t sC)   // per-batch element strides (z dim)
{
    const int BM = 64, BN = 64, BK = 16;
    __shared__ float As[BK][BM + 4];   // +4 pad: alignment-safe, fewer STS conflicts
    __shared__ float Bs[BK][BN];

    const int bz = blockIdx.z;
    const int m0 = blockIdx.y * BM;
    const int n0 = blockIdx.x * BN;
    const float* Ab = A  + (size_t)bz * sA;
    const float* Bw = Bm + (size_t)bz * sB;
    float*       Cb = C  + (size_t)bz * sC;

    const int tid = threadIdx.x;
    const int tx  = tid & 15;    // output col group
    const int ty  = tid >> 4;    // output row group

    // loader mapping
    const int lam = tid >> 2;          // 0..63 : A row within tile
    const int lak = (tid & 3) * 4;     // 0,4,8,12 : A col group
    const int lbk = tid >> 4;          // 0..15 : B row within tile
    const int lbn = (tid & 15) * 4;    // B col group

    float acc[4][4] = {};

    const int KT = DUAL ? 2 * K : K;
    for (int kt = 0; kt < KT; kt += BK) {
        const float* Asrc; const float* Bsrc; int k0;
        if (DUAL && kt >= K) { Asrc = A2; Bsrc = B2; k0 = kt - K; }
        else                 { Asrc = Ab; Bsrc = Bw; k0 = kt;     }

        float4 av = *reinterpret_cast<const float4*>(
            Asrc + (size_t)(m0 + lam) * K + (k0 + lak));
        float4 bv = *reinterpret_cast<const float4*>(
            Bsrc + (size_t)(k0 + lbk) * N + (n0 + lbn));

        __syncthreads();   // protect previous tile's reads
        As[lak + 0][lam] = av.x;
        As[lak + 1][lam] = av.y;
        As[lak + 2][lam] = av.z;
        As[lak + 3][lam] = av.w;
        *reinterpret_cast<float4*>(&Bs[lbk][lbn]) = bv;
        __syncthreads();

        #pragma unroll
        for (int kk = 0; kk < BK; kk++) {
            float a[4], b[4];
            *reinterpret_cast<float4*>(a) =
                *reinterpret_cast<const float4*>(&As[kk][ty * 4]);
            *reinterpret_cast<float4*>(b) =
                *reinterpret_cast<const float4*>(&Bs[kk][tx * 4]);
            #pragma unroll
            for (int i = 0; i < 4; i++)
                #pragma unroll
                for (int j = 0; j < 4; j++)
                    acc[i][j] = fmaf(a[i], b[j], acc[i][j]);
        }
    }

    // epilogue
    float bb[4];
    if (BIAS) {
        *reinterpret_cast<float4*>(bb) =
            *reinterpret_cast<const float4*>(bias + n0 + tx * 4);
    }
    #pragma unroll
    for (int i = 0; i < 4; i++) {
        const int row = m0 + ty * 4 + i;
        float rs = 1.0f;
        if (ROWSCALE) rs = g_deg[row];   // only used when M == Nn
        float4 o;
        float* ov = &o.x;
        #pragma unroll
        for (int j = 0; j < 4; j++) {
            float v = acc[i][j];
            if (ROWSCALE) v *= rs;
            if (BIAS)     v += bb[j];
            if (RELU)     v = fmaxf(v, 0.f);
            ov[j] = v;
        }
        *reinterpret_cast<float4*>(Cb + (size_t)row * N + n0 + tx * 4) = o;
    }
}

// ---------------------------------------------------------------------------
extern "C" void kernel_launch(void* const* d_in, const int* in_sizes, int n_in,
                              void* d_out, int out_size)
{
    (void)in_sizes; (void)n_in; (void)out_size;
    const float* x      = (const float*)d_in[0];
    const float* adj    = (const float*)d_in[1];
    const float* W_mlp2 = (const float*)d_in[2];
    const float* b_mlp2 = (const float*)d_in[3];
    const float* Wr1    = (const float*)d_in[4];
    const float* Wo1    = (const float*)d_in[5];
    const float* b1     = (const float*)d_in[6];
    const float* Wr2    = (const float*)d_in[7];
    const float* Wo2    = (const float*)d_in[8];
    const float* b2     = (const float*)d_in[9];
    const float* Wr3    = (const float*)d_in[10];
    const float* Wo3    = (const float*)d_in[11];
    const float* b3     = (const float*)d_in[12];
    const float* W_mlp1 = (const float*)d_in[13];
    const float* b_mlp1 = (const float*)d_in[14];
    float* out = (float*)d_out;

    float *h0, *h1, *agg;
    cudaGetSymbolAddress((void**)&h0,  g_buf0);
    cudaGetSymbolAddress((void**)&h1,  g_buf1);
    cudaGetSymbolAddress((void**)&agg, g_agg);

    const size_t sHD = (size_t)Nn * Dd;   // per-batch stride of h / agg

    // 1) degree reciprocals
    deg_kernel<<<Nn, 256>>>(adj);

    // 2) h0 = x @ W_mlp2 + b_mlp2     (M=8192, N=128, K=1536)
    gemm_k<false, false, false, true><<<dim3(Dd/64, MT/64, 1), 256>>>(
        x, W_mlp2, nullptr, nullptr, b_mlp2, h0, MT, Dd, LD_, 0, 0, 0);

    // ---- SAGE layer 1 ----
    gemm_k<false, false, true, false><<<dim3(Dd/64, Nn/64, Bb), 256>>>(
        adj, h0, nullptr, nullptr, nullptr, agg, Nn, Dd, Nn, 0, sHD, sHD);
    gemm_k<true, true, false, true><<<dim3(Dd/64, MT/64, 1), 256>>>(
        agg, Wr1, h0, Wo1, b1, h1, MT, Dd, Dd, 0, 0, 0);

    // ---- SAGE layer 2 ----
    gemm_k<false, false, true, false><<<dim3(Dd/64, Nn/64, Bb), 256>>>(
        adj, h1, nullptr, nullptr, nullptr, agg, Nn, Dd, Nn, 0, sHD, sHD);
    gemm_k<true, true, false, true><<<dim3(Dd/64, MT/64, 1), 256>>>(
        agg, Wr2, h1, Wo2, b2, h0, MT, Dd, Dd, 0, 0, 0);

    // ---- SAGE layer 3 (no relu) ----
    gemm_k<false, false, true, false><<<dim3(Dd/64, Nn/64, Bb), 256>>>(
        adj, h0, nullptr, nullptr, nullptr, agg, Nn, Dd, Nn, 0, sHD, sHD);
    gemm_k<true, false, false, true><<<dim3(Dd/64, MT/64, 1), 256>>>(
        agg, Wr3, h0, Wo3, b3, h1, MT, Dd, Dd, 0, 0, 0);

    // 3) out = h1 @ W_mlp1 + b_mlp1   (M=8192, N=1536, K=128)
    gemm_k<false, false, false, true><<<dim3(LD_/64, MT/64, 1), 256>>>(
        h1, W_mlp1, nullptr, nullptr, b_mlp1, out, MT, LD_, Dd, 0, 0, 0);
}

// round 4
// speedup vs baseline: 2.1166x; 2.1166x over previous
#include <cuda_runtime.h>
#include <cuda_bf16.h>
#include <cstdint>

#define Bb   4
#define Nn   2048
#define Ll   12
#define Dd   128
#define LD_  (Ll*Dd)      // 1536
#define MT   (Bb*Nn)      // 8192

typedef __nv_bfloat16 bf16;

// ---------------- scratch (device globals; no allocation) -------------------
__device__ float g_h0 [MT * Dd];
__device__ float g_h1 [MT * Dd];
__device__ bf16  g_h0h[MT * Dd];  __device__ bf16 g_h0l[MT * Dd];
__device__ bf16  g_h1h[MT * Dd];  __device__ bf16 g_h1l[MT * Dd];
__device__ bf16  g_aggh[MT * Dd]; __device__ bf16 g_aggl[MT * Dd];
__device__ bf16  g_hTh[Bb * Dd * Nn]; __device__ bf16 g_hTl[Bb * Dd * Nn];
__device__ bf16  g_adjh[Nn * Nn]; __device__ bf16 g_adjl[Nn * Nn];
__device__ bf16  g_xh [MT * LD_]; __device__ bf16 g_xl [MT * LD_];
__device__ bf16  g_W2h[Dd * LD_]; __device__ bf16 g_W2l[Dd * LD_];
__device__ bf16  g_W1h[LD_ * Dd]; __device__ bf16 g_W1l[LD_ * Dd];
__device__ bf16  g_Wrh[3][Dd * Dd]; __device__ bf16 g_Wrl[3][Dd * Dd];
__device__ bf16  g_Woh[3][Dd * Dd]; __device__ bf16 g_Wol[3][Dd * Dd];
__device__ float g_deg[Nn];

// ---------------- helpers ----------------------------------------------------
__device__ __forceinline__ uint32_t smem_u32(const void* p) {
    uint32_t a;
    asm("{ .reg .u64 t; cvta.to.shared.u64 t, %1; cvt.u32.u64 %0, t; }"
        : "=r"(a) : "l"(p));
    return a;
}
__device__ __forceinline__ void cp_async16(uint32_t dst, const void* src) {
    asm volatile("cp.async.cg.shared.global [%0], [%1], 16;"
                 :: "r"(dst), "l"(src) : "memory");
}
__device__ __forceinline__ void cp_commit() {
    asm volatile("cp.async.commit_group;" ::: "memory");
}
template<int N_>
__device__ __forceinline__ void cp_wait() {
    asm volatile("cp.async.wait_group %0;" :: "n"(N_) : "memory");
}
__device__ __forceinline__ void ldmx4(uint32_t* r, uint32_t addr) {
    asm volatile("ldmatrix.sync.aligned.m8n8.x4.shared.b16 {%0,%1,%2,%3}, [%4];"
                 : "=r"(r[0]), "=r"(r[1]), "=r"(r[2]), "=r"(r[3]) : "r"(addr));
}
__device__ __forceinline__ void mma_bf16(float* c, const uint32_t* a, const uint32_t* b) {
    asm volatile(
        "mma.sync.aligned.m16n8k16.row.col.f32.bf16.bf16.f32 "
        "{%0,%1,%2,%3}, {%4,%5,%6,%7}, {%8,%9}, {%0,%1,%2,%3};"
        : "+f"(c[0]), "+f"(c[1]), "+f"(c[2]), "+f"(c[3])
        : "r"(a[0]), "r"(a[1]), "r"(a[2]), "r"(a[3]), "r"(b[0]), "r"(b[1]));
}
__device__ __forceinline__ void split2(float v, bf16& h, bf16& l) {
    h = __float2bfloat16(v);
    l = __float2bfloat16(v - __bfloat162float(h));
}

// ---------------- small kernels ----------------------------------------------
__global__ void deg_kernel(const float* __restrict__ adj) {
    int row = blockIdx.x;
    const float* r = adj + (size_t)row * Nn;
    float s = 0.f;
    for (int i = threadIdx.x; i < Nn; i += blockDim.x) s += r[i];
    __shared__ float sm[8];
    #pragma unroll
    for (int o = 16; o > 0; o >>= 1) s += __shfl_down_sync(0xffffffffu, s, o);
    if ((threadIdx.x & 31) == 0) sm[threadIdx.x >> 5] = s;
    __syncthreads();
    if (threadIdx.x == 0) {
        float t = 0.f;
        #pragma unroll
        for (int i = 0; i < 8; i++) t += sm[i];
        g_deg[row] = 1.0f / fmaxf(t, 1.0f);
    }
}

__global__ void adj_split_kernel(const float* __restrict__ adj) {
    int idx = blockIdx.x * blockDim.x + threadIdx.x;   // covers Nn*Nn
    int row = idx >> 11;
    float v = adj[idx] * g_deg[row];
    split2(v, g_adjh[idx], g_adjl[idx]);
}

__global__ void x_split_kernel(const float2* __restrict__ in) {
    int idx = blockIdx.x * blockDim.x + threadIdx.x;   // covers MT*LD_/2
    float2 v = in[idx];
    bf16 h0, l0, h1, l1;
    split2(v.x, h0, l0); split2(v.y, h1, l1);
    *reinterpret_cast<__nv_bfloat162*>(&g_xh[2 * idx]) = __nv_bfloat162(h0, h1);
    *reinterpret_cast<__nv_bfloat162*>(&g_xl[2 * idx]) = __nv_bfloat162(l0, l1);
}

// dst_{h,l}[C x R] = split( src[R x C]^T )  (32x32 tiles, 32x8 threads, batch z)
__global__ void transpose_split(const float* __restrict__ src,
                                bf16* __restrict__ dh, bf16* __restrict__ dl,
                                int R, int C, size_t sS, size_t sD) {
    __shared__ float t[32][33];
    const float* s = src + (size_t)blockIdx.z * sS;
    bf16* dhb = dh + (size_t)blockIdx.z * sD;
    bf16* dlb = dl + (size_t)blockIdx.z * sD;
    int c0 = blockIdx.x * 32, r0 = blockIdx.y * 32;
    int x = threadIdx.x, y = threadIdx.y;
    #pragma unroll
    for (int i = 0; i < 32; i += 8)
        t[y + i][x] = s[(size_t)(r0 + y + i) * C + c0 + x];
    __syncthreads();
    #pragma unroll
    for (int i = 0; i < 32; i += 8) {
        bf16 h, l;
        split2(t[x][y + i], h, l);
        size_t o = (size_t)(c0 + y + i) * R + r0 + x;
        dhb[o] = h; dlb[o] = l;
    }
}

// ---------------- bf16x2 tensor-core GEMM -------------------------------------
// C = epi( A @ Bw^T [ + A2 @ B2^T ] ), operands pre-split hi/lo bf16 [rows][K1].
// CTA 64x128, BK=32, 3-stage cp.async, 256 thr (8 warps 2Mx4N), warp 32x32.
#define STAGES 3
#define BM 64
#define BN 128
#define BK 32
#define KS2 40                              // padded row stride (halves), 80 B
#define OFF_AL (64 * KS2)                   // 2560 halves
#define OFF_BH (2 * 64 * KS2)               // 5120
#define OFF_BL (OFF_BH + 128 * KS2)         // 10240
#define STAGE_H (OFF_BL + 128 * KS2)        // 15360 halves = 30720 B
#define GEMM_SMEM (STAGES * STAGE_H * 2)    // 92160 B

template<bool DUAL, bool RELU, bool BIAS, bool WF32, bool WSPL>
__global__ void __launch_bounds__(256, 2)
gemm_bf(const bf16* __restrict__ Ah, const bf16* __restrict__ Al,
        const bf16* __restrict__ Bh, const bf16* __restrict__ Bl,
        const bf16* __restrict__ A2h, const bf16* __restrict__ A2l,
        const bf16* __restrict__ B2h, const bf16* __restrict__ B2l,
        const float* __restrict__ bias,
        float* __restrict__ Cf, bf16* __restrict__ Ch, bf16* __restrict__ Cl,
        int N, int K1, size_t sA, size_t sB, size_t sC)
{
    extern __shared__ bf16 smem[];
    const uint32_t sbase = smem_u32(smem);
    const int tid = threadIdx.x;
    const int lane = tid & 31, wid = tid >> 5;
    const int warpM = wid & 1, warpN = wid >> 1;
    const int gid = lane >> 2, tg = lane & 3;

    const int m0 = blockIdx.y * BM, n0 = blockIdx.x * BN, bz = blockIdx.z;
    const bf16* pAh = Ah + (size_t)bz * sA;
    const bf16* pAl = Al + (size_t)bz * sA;
    const bf16* pBh = Bh + (size_t)bz * sB;
    const bf16* pBl = Bl + (size_t)bz * sB;

    const int nk1 = K1 / BK;
    const int nk  = DUAL ? 2 * nk1 : nk1;

    auto issue = [&](int tile, int s) {
        const bf16 *ah, *al, *bh, *bl; int k0;
        if (DUAL && tile >= nk1) { ah = A2h; al = A2l; bh = B2h; bl = B2l;
                                   k0 = (tile - nk1) * BK; }
        else { ah = pAh; al = pAl; bh = pBh; bl = pBl; k0 = tile * BK; }
        const uint32_t st = sbase + s * (STAGE_H * 2);
        {   // A: 64 rows x 4 chunks, 256 threads -> 1 each (hi + lo)
            int row = tid >> 2, c = tid & 3;
            uint32_t dof = (uint32_t)(row * KS2 + c * 8) * 2;
            size_t gof = (size_t)(m0 + row) * K1 + k0 + c * 8;
            cp_async16(st + dof,              ah + gof);
            cp_async16(st + OFF_AL * 2 + dof, al + gof);
        }
        #pragma unroll
        for (int i = 0; i < 2; i++) {  // B: 128 rows x 4 chunks
            int idx = tid + i * 256;
            int row = idx >> 2, c = idx & 3;
            uint32_t dof = (uint32_t)(row * KS2 + c * 8) * 2;
            size_t gof = (size_t)(n0 + row) * K1 + k0 + c * 8;
            cp_async16(st + OFF_BH * 2 + dof, bh + gof);
            cp_async16(st + OFF_BL * 2 + dof, bl + gof);
        }
        cp_commit();
    };

    float acc[2][4][4];
    #pragma unroll
    for (int mi = 0; mi < 2; mi++)
        #pragma unroll
        for (int ni = 0; ni < 4; ni++)
            #pragma unroll
            for (int j = 0; j < 4; j++) acc[mi][ni][j] = 0.f;

    // ldmatrix per-lane offsets
    const int ar = lane & 15, ak = (lane >> 4) * 8;
    const uint32_t a_off = (uint32_t)((warpM * 32 + ar) * KS2 + ak) * 2;
    const int nr = (lane & 7) + ((lane >> 4) * 8);
    const int bk = ((lane >> 3) & 1) * 8;
    const uint32_t b_off = (uint32_t)((warpN * 32 + nr) * KS2 + bk) * 2;

    #pragma unroll
    for (int s = 0; s < STAGES - 1; s++) issue(s, s);

    for (int kt = 0; kt < nk; ++kt) {
        cp_wait<STAGES - 2>();
        __syncthreads();
        if (kt + STAGES - 1 < nk) issue(kt + STAGES - 1, (kt + STAGES - 1) % STAGES);

        const uint32_t st = sbase + (kt % STAGES) * (STAGE_H * 2);
        const uint32_t aA = st + a_off;
        const uint32_t aB = st + OFF_BH * 2 + b_off;

        #pragma unroll
        for (int ks = 0; ks < 2; ks++) {
            const uint32_t ko = ks * 32;   // 16 halves
            uint32_t ah_[2][4], al_[2][4], bh_[2][4], bl_[2][4];
            #pragma unroll
            for (int mi = 0; mi < 2; mi++) {
                ldmx4(ah_[mi], aA + mi * (16 * KS2 * 2) + ko);
                ldmx4(al_[mi], aA + OFF_AL * 2 + mi * (16 * KS2 * 2) + ko);
            }
            #pragma unroll
            for (int np = 0; np < 2; np++) {
                ldmx4(bh_[np], aB + np * (16 * KS2 * 2) + ko);
                ldmx4(bl_[np], aB + (OFF_BL - OFF_BH) * 2 + np * (16 * KS2 * 2) + ko);
            }
            #pragma unroll
            for (int mi = 0; mi < 2; mi++)
                #pragma unroll
                for (int ni = 0; ni < 4; ni++) {
                    const int np = ni >> 1, jo = (ni & 1) * 2;
                    mma_bf16(acc[mi][ni], ah_[mi], &bh_[np][jo]);
                    mma_bf16(acc[mi][ni], ah_[mi], &bl_[np][jo]);
                    mma_bf16(acc[mi][ni], al_[mi], &bh_[np][jo]);
                }
        }
    }
    cp_wait<0>();

    // epilogue
    #pragma unroll
    for (int mi = 0; mi < 2; mi++) {
        const int row = m0 + warpM * 32 + mi * 16 + gid;
        #pragma unroll
        for (int ni = 0; ni < 4; ni++) {
            const int col = n0 + warpN * 32 + ni * 8 + 2 * tg;
            float* c = acc[mi][ni];
            float b0 = 0.f, b1 = 0.f;
            if (BIAS) { b0 = bias[col]; b1 = bias[col + 1]; }
            #pragma unroll
            for (int h = 0; h < 2; h++) {
                float v0 = c[2 * h + 0] + b0;
                float v1 = c[2 * h + 1] + b1;
                if (RELU) { v0 = fmaxf(v0, 0.f); v1 = fmaxf(v1, 0.f); }
                size_t o = (size_t)(row + 8 * h) * N + col + (size_t)bz * sC;
                if (WF32)
                    *reinterpret_cast<float2*>(Cf + o) = make_float2(v0, v1);
                if (WSPL) {
                    bf16 h0, l0, h1, l1;
                    split2(v0, h0, l0); split2(v1, h1, l1);
                    *reinterpret_cast<__nv_bfloat162*>(Ch + o) = __nv_bfloat162(h0, h1);
                    *reinterpret_cast<__nv_bfloat162*>(Cl + o) = __nv_bfloat162(l0, l1);
                }
            }
        }
    }
}

// ---------------- launch --------------------------------------------------------
extern "C" void kernel_launch(void* const* d_in, const int* in_sizes, int n_in,
                              void* d_out, int out_size)
{
    (void)in_sizes; (void)n_in; (void)out_size;
    const float* x      = (const float*)d_in[0];
    const float* adj    = (const float*)d_in[1];
    const float* W_mlp2 = (const float*)d_in[2];
    const float* b_mlp2 = (const float*)d_in[3];
    const float* Wr[3]  = {(const float*)d_in[4], (const float*)d_in[7], (const float*)d_in[10]};
    const float* Wo[3]  = {(const float*)d_in[5], (const float*)d_in[8], (const float*)d_in[11]};
    const float* bs[3]  = {(const float*)d_in[6], (const float*)d_in[9], (const float*)d_in[12]};
    const float* W_mlp1 = (const float*)d_in[13];
    const float* b_mlp1 = (const float*)d_in[14];
    float* out = (float*)d_out;

    float *h0, *h1;
    bf16 *h0h, *h0l, *h1h, *h1l, *aggh, *aggl, *hTh, *hTl;
    bf16 *xh, *xl, *W2h, *W2l, *W1h, *W1l, *Wrh, *Wrl, *Woh, *Wol;
    cudaGetSymbolAddress((void**)&h0,   g_h0);
    cudaGetSymbolAddress((void**)&h1,   g_h1);
    cudaGetSymbolAddress((void**)&h0h,  g_h0h); cudaGetSymbolAddress((void**)&h0l, g_h0l);
    cudaGetSymbolAddress((void**)&h1h,  g_h1h); cudaGetSymbolAddress((void**)&h1l, g_h1l);
    cudaGetSymbolAddress((void**)&aggh, g_aggh); cudaGetSymbolAddress((void**)&aggl, g_aggl);
    cudaGetSymbolAddress((void**)&hTh,  g_hTh); cudaGetSymbolAddress((void**)&hTl, g_hTl);
    cudaGetSymbolAddress((void**)&xh,   g_xh);  cudaGetSymbolAddress((void**)&xl,  g_xl);
    cudaGetSymbolAddress((void**)&W2h,  g_W2h); cudaGetSymbolAddress((void**)&W2l, g_W2l);
    cudaGetSymbolAddress((void**)&W1h,  g_W1h); cudaGetSymbolAddress((void**)&W1l, g_W1l);
    cudaGetSymbolAddress((void**)&Wrh,  g_Wrh); cudaGetSymbolAddress((void**)&Wrl, g_Wrl);
    cudaGetSymbolAddress((void**)&Woh,  g_Woh); cudaGetSymbolAddress((void**)&Wol, g_Wol);
    bf16* adjh; bf16* adjl;
    cudaGetSymbolAddress((void**)&adjh, g_adjh); cudaGetSymbolAddress((void**)&adjl, g_adjl);

    cudaFuncSetAttribute(gemm_bf<false, false, true,  true,  true >,
                         cudaFuncAttributeMaxDynamicSharedMemorySize, GEMM_SMEM);
    cudaFuncSetAttribute(gemm_bf<false, false, false, false, true >,
                         cudaFuncAttributeMaxDynamicSharedMemorySize, GEMM_SMEM);
    cudaFuncSetAttribute(gemm_bf<true,  true,  true,  true,  true >,
                         cudaFuncAttributeMaxDynamicSharedMemorySize, GEMM_SMEM);
    cudaFuncSetAttribute(gemm_bf<true,  false, true,  true,  true >,
                         cudaFuncAttributeMaxDynamicSharedMemorySize, GEMM_SMEM);
    cudaFuncSetAttribute(gemm_bf<false, false, true,  true,  false>,
                         cudaFuncAttributeMaxDynamicSharedMemorySize, GEMM_SMEM);

    const size_t sHD = (size_t)Nn * Dd;
    const dim3 T32(32, 8);

    // preprocessing
    deg_kernel<<<Nn, 256>>>(adj);
    adj_split_kernel<<<(Nn * Nn) / 256, 256>>>(adj);
    x_split_kernel<<<(MT * LD_ / 2) / 256, 256>>>((const float2*)x);
    transpose_split<<<dim3(Dd / 32, LD_ / 32, 1), T32>>>(W_mlp2, W2h, W2l, LD_, Dd, 0, 0);
    transpose_split<<<dim3(LD_ / 32, Dd / 32, 1), T32>>>(W_mlp1, W1h, W1l, Dd, LD_, 0, 0);
    for (int l = 0; l < 3; l++) {
        transpose_split<<<dim3(4, 4, 1), T32>>>(Wr[l], Wrh + l * Dd * Dd, Wrl + l * Dd * Dd, Dd, Dd, 0, 0);
        transpose_split<<<dim3(4, 4, 1), T32>>>(Wo[l], Woh + l * Dd * Dd, Wol + l * Dd * Dd, Dd, Dd, 0, 0);
    }

    // mlp2: h0 = x @ W_mlp2 + b   (M=8192, N=128, K=1536)
    gemm_bf<false, false, true, true, true><<<dim3(1, MT / BM, 1), 256, GEMM_SMEM>>>(
        xh, xl, W2h, W2l, nullptr, nullptr, nullptr, nullptr,
        b_mlp2, h0, h0h, h0l, Dd, LD_, 0, 0, 0);

    float* hinf = h0;  bf16* hinh = h0h; bf16* hinl = h0l;
    float* houtf = h1; bf16* houth = h1h; bf16* houtl = h1l;
    for (int l = 0; l < 3; l++) {
        // hT = split(hin^T) per batch
        transpose_split<<<dim3(Dd / 32, Nn / 32, Bb), T32>>>(hinf, hTh, hTl, Nn, Dd, sHD, sHD);
        // agg = adjn @ hin  (per batch; M=2048, N=128, K=2048)
        gemm_bf<false, false, false, false, true><<<dim3(1, Nn / BM, Bb), 256, GEMM_SMEM>>>(
            adjh, adjl, hTh, hTl, nullptr, nullptr, nullptr, nullptr,
            nullptr, nullptr, aggh, aggl, Dd, Nn, 0, sHD, sHD);
        // h' = act(agg@Wr + hin@Wo + b)  (M=8192, N=128, dual K=128+128)
        if (l < 2)
            gemm_bf<true, true, true, true, true><<<dim3(1, MT / BM, 1), 256, GEMM_SMEM>>>(
                aggh, aggl, Wrh + l * Dd * Dd, Wrl + l * Dd * Dd,
                hinh, hinl, Woh + l * Dd * Dd, Wol + l * Dd * Dd,
                bs[l], houtf, houth, houtl, Dd, Dd, 0, 0, 0);
        else
            gemm_bf<true, false, true, true, true><<<dim3(1, MT / BM, 1), 256, GEMM_SMEM>>>(
                aggh, aggl, Wrh + l * Dd * Dd, Wrl + l * Dd * Dd,
                hinh, hinl, Woh + l * Dd * Dd, Wol + l * Dd * Dd,
                bs[l], houtf, houth, houtl, Dd, Dd, 0, 0, 0);
        { float* tf = hinf; hinf = houtf; houtf = tf; }
        { bf16* t = hinh; hinh = houth; houth = t; }
        { bf16* t = hinl; hinl = houtl; houtl = t; }
    }

    // mlp1: out = hin @ W_mlp1 + b   (M=8192, N=1536, K=128)
    gemm_bf<false, false, true, true, false><<<dim3(LD_ / BN, MT / BM, 1), 256, GEMM_SMEM>>>(
        hinh, hinl, W1h, W1l, nullptr, nullptr, nullptr, nullptr,
        b_mlp1, out, nullptr, nullptr, LD_, Dd, 0, 0, 0);
}

// round 5
// speedup vs baseline: 2.2822x; 1.0782x over previous
#include <cuda_runtime.h>
#include <cuda_bf16.h>
#include <cstdint>

#define Bb   4
#define Nn   2048
#define Ll   12
#define Dd   128
#define LD_  (Ll*Dd)      // 1536
#define MT   (Bb*Nn)      // 8192

typedef __nv_bfloat16 bf16;

// ---------------- scratch (device globals; no allocation) -------------------
__device__ bf16  g_h0h[MT * Dd];  __device__ bf16 g_h0l[MT * Dd];
__device__ bf16  g_h1h[MT * Dd];  __device__ bf16 g_h1l[MT * Dd];
__device__ bf16  g_aggh[MT * Dd]; __device__ bf16 g_aggl[MT * Dd];
__device__ bf16  g_hTh[Bb * Dd * Nn]; __device__ bf16 g_hTl[Bb * Dd * Nn];
__device__ bf16  g_adjh[Nn * Nn]; __device__ bf16 g_adjl[Nn * Nn];
__device__ bf16  g_xh [MT * LD_]; __device__ bf16 g_xl [MT * LD_];
__device__ bf16  g_W2h[Dd * LD_]; __device__ bf16 g_W2l[Dd * LD_];
__device__ bf16  g_W1h[LD_ * Dd]; __device__ bf16 g_W1l[LD_ * Dd];
__device__ bf16  g_Wrh[3][Dd * Dd]; __device__ bf16 g_Wrl[3][Dd * Dd];
__device__ bf16  g_Woh[3][Dd * Dd]; __device__ bf16 g_Wol[3][Dd * Dd];

// ---------------- helpers ----------------------------------------------------
__device__ __forceinline__ uint32_t smem_u32(const void* p) {
    uint32_t a;
    asm("{ .reg .u64 t; cvta.to.shared.u64 t, %1; cvt.u32.u64 %0, t; }"
        : "=r"(a) : "l"(p));
    return a;
}
__device__ __forceinline__ void cp_async16(uint32_t dst, const void* src) {
    asm volatile("cp.async.cg.shared.global [%0], [%1], 16;"
                 :: "r"(dst), "l"(src) : "memory");
}
__device__ __forceinline__ void cp_commit() {
    asm volatile("cp.async.commit_group;" ::: "memory");
}
template<int N_>
__device__ __forceinline__ void cp_wait() {
    asm volatile("cp.async.wait_group %0;" :: "n"(N_) : "memory");
}
__device__ __forceinline__ void ldmx4(uint32_t* r, uint32_t addr) {
    asm volatile("ldmatrix.sync.aligned.m8n8.x4.shared.b16 {%0,%1,%2,%3}, [%4];"
                 : "=r"(r[0]), "=r"(r[1]), "=r"(r[2]), "=r"(r[3]) : "r"(addr));
}
__device__ __forceinline__ void mma_bf16(float* c, const uint32_t* a, const uint32_t* b) {
    asm volatile(
        "mma.sync.aligned.m16n8k16.row.col.f32.bf16.bf16.f32 "
        "{%0,%1,%2,%3}, {%4,%5,%6,%7}, {%8,%9}, {%0,%1,%2,%3};"
        : "+f"(c[0]), "+f"(c[1]), "+f"(c[2]), "+f"(c[3])
        : "r"(a[0]), "r"(a[1]), "r"(a[2]), "r"(a[3]), "r"(b[0]), "r"(b[1]));
}
__device__ __forceinline__ void split2(float v, bf16& h, bf16& l) {
    h = __float2bfloat16(v);
    l = __float2bfloat16(v - __bfloat162float(h));
}

// ---------------- fused preprocessing ------------------------------------------
// One block per adj row: row-sum, clip, scale, split. Single pass.
__global__ void adj_fused(const float* __restrict__ adj) {
    const int row = blockIdx.x;
    const int tid = threadIdx.x;
    const float* r = adj + (size_t)row * Nn;
    float v[8]; float s = 0.f;
    #pragma unroll
    for (int i = 0; i < 8; i++) { v[i] = r[tid + i * 256]; s += v[i]; }
    __shared__ float sm[8];
    #pragma unroll
    for (int o = 16; o > 0; o >>= 1) s += __shfl_down_sync(0xffffffffu, s, o);
    if ((tid & 31) == 0) sm[tid >> 5] = s;
    __syncthreads();
    __shared__ float rdeg;
    if (tid == 0) {
        float t = 0.f;
        #pragma unroll
        for (int i = 0; i < 8; i++) t += sm[i];
        rdeg = 1.0f / fmaxf(t, 1.0f);
    }
    __syncthreads();
    const float rd = rdeg;
    #pragma unroll
    for (int i = 0; i < 8; i++) {
        bf16 h, l;
        split2(v[i] * rd, h, l);
        size_t o = (size_t)row * Nn + tid + i * 256;
        g_adjh[o] = h; g_adjl[o] = l;
    }
}

__global__ void x_split_kernel(const float2* __restrict__ in) {
    int idx = blockIdx.x * blockDim.x + threadIdx.x;   // covers MT*LD_/2
    float2 v = in[idx];
    bf16 h0, l0, h1, l1;
    split2(v.x, h0, l0); split2(v.y, h1, l1);
    *reinterpret_cast<__nv_bfloat162*>(&g_xh[2 * idx]) = __nv_bfloat162(h0, h1);
    *reinterpret_cast<__nv_bfloat162*>(&g_xl[2 * idx]) = __nv_bfloat162(l0, l1);
}

// All 8 weight transposes in ONE launch. 480 tile-blocks of 32x32, 32x8 threads.
__global__ void wtrans_all(const float* __restrict__ W2, const float* __restrict__ W1,
                           const float* __restrict__ Wr0, const float* __restrict__ Wo0,
                           const float* __restrict__ Wr1, const float* __restrict__ Wo1,
                           const float* __restrict__ Wr2, const float* __restrict__ Wo2)
{
    __shared__ float t[32][33];
    const int tb = blockIdx.x;
    const float* src; bf16* dh; bf16* dl; int R, C, tx, ty;
    if (tb < 192) {                       // W_mlp2: [1536 x 128] -> [128 x 1536]
        src = W2; dh = g_W2h; dl = g_W2l; R = LD_; C = Dd;
        ty = tb / 4; tx = tb % 4;
    } else if (tb < 384) {                // W_mlp1: [128 x 1536] -> [1536 x 128]
        src = W1; dh = g_W1h; dl = g_W1l; R = Dd; C = LD_;
        int u = tb - 192; ty = u / 48; tx = u % 48;
    } else {                              // Wr/Wo[l]: [128 x 128]
        int u = tb - 384; int l = u / 32; int v = u % 32;
        const float* wsrc[6] = {Wr0, Wo0, Wr1, Wo1, Wr2, Wo2};
        src = wsrc[l * 2 + (v < 16 ? 0 : 1)];
        if (v < 16) { dh = g_Wrh[l]; dl = g_Wrl[l]; }
        else        { dh = g_Woh[l]; dl = g_Wol[l]; }
        int w = v & 15; tx = w % 4; ty = w / 4; R = Dd; C = Dd;
    }
    const int c0 = tx * 32, r0 = ty * 32;
    const int x = threadIdx.x, y = threadIdx.y;
    #pragma unroll
    for (int i = 0; i < 32; i += 8)
        t[y + i][x] = src[(size_t)(r0 + y + i) * C + c0 + x];
    __syncthreads();
    #pragma unroll
    for (int i = 0; i < 32; i += 8) {
        bf16 h, l;
        split2(t[x][y + i], h, l);
        size_t o = (size_t)(c0 + y + i) * R + r0 + x;
        dh[o] = h; dl[o] = l;
    }
}

// ---------------- bf16x2 tensor-core GEMM -------------------------------------
// C = epi( A @ Bw^T [ + A2 @ B2^T ] ), operands pre-split hi/lo bf16 [rows][K1].
// CTA 64x128, BK=32, 3-stage cp.async, 256 thr (8 warps 2Mx4N), warp 32x32.
#define STAGES 3
#define BM 64
#define BN 128
#define BK 32
#define KS2 40
#define OFF_AL (64 * KS2)
#define OFF_BH (2 * 64 * KS2)
#define OFF_BL (OFF_BH + 128 * KS2)
#define STAGE_H (OFF_BL + 128 * KS2)
#define GEMM_SMEM (STAGES * STAGE_H * 2)    // 92160 B

template<bool DUAL, bool RELU, bool BIAS, bool WF32, bool WSPL, bool WT>
__global__ void __launch_bounds__(256, 2)
gemm_bf(const bf16* __restrict__ Ah, const bf16* __restrict__ Al,
        const bf16* __restrict__ Bh, const bf16* __restrict__ Bl,
        const bf16* __restrict__ A2h, const bf16* __restrict__ A2l,
        const bf16* __restrict__ B2h, const bf16* __restrict__ B2l,
        const float* __restrict__ bias,
        float* __restrict__ Cf, bf16* __restrict__ Ch, bf16* __restrict__ Cl,
        bf16* __restrict__ Th, bf16* __restrict__ Tl,
        int N, int K1, size_t sA, size_t sB, size_t sC)
{
    extern __shared__ bf16 smem[];
    const uint32_t sbase = smem_u32(smem);
    const int tid = threadIdx.x;
    const int lane = tid & 31, wid = tid >> 5;
    const int warpM = wid & 1, warpN = wid >> 1;
    const int gid = lane >> 2, tg = lane & 3;

    const int m0 = blockIdx.y * BM, n0 = blockIdx.x * BN, bz = blockIdx.z;
    const bf16* pAh = Ah + (size_t)bz * sA;
    const bf16* pAl = Al + (size_t)bz * sA;
    const bf16* pBh = Bh + (size_t)bz * sB;
    const bf16* pBl = Bl + (size_t)bz * sB;

    const int nk1 = K1 / BK;
    const int nk  = DUAL ? 2 * nk1 : nk1;

    auto issue = [&](int tile, int s) {
        const bf16 *ah, *al, *bh, *bl; int k0;
        if (DUAL && tile >= nk1) { ah = A2h; al = A2l; bh = B2h; bl = B2l;
                                   k0 = (tile - nk1) * BK; }
        else { ah = pAh; al = pAl; bh = pBh; bl = pBl; k0 = tile * BK; }
        const uint32_t st = sbase + s * (STAGE_H * 2);
        {
            int row = tid >> 2, c = tid & 3;
            uint32_t dof = (uint32_t)(row * KS2 + c * 8) * 2;
            size_t gof = (size_t)(m0 + row) * K1 + k0 + c * 8;
            cp_async16(st + dof,              ah + gof);
            cp_async16(st + OFF_AL * 2 + dof, al + gof);
        }
        #pragma unroll
        for (int i = 0; i < 2; i++) {
            int idx = tid + i * 256;
            int row = idx >> 2, c = idx & 3;
            uint32_t dof = (uint32_t)(row * KS2 + c * 8) * 2;
            size_t gof = (size_t)(n0 + row) * K1 + k0 + c * 8;
            cp_async16(st + OFF_BH * 2 + dof, bh + gof);
            cp_async16(st + OFF_BL * 2 + dof, bl + gof);
        }
        cp_commit();
    };

    float acc[2][4][4];
    #pragma unroll
    for (int mi = 0; mi < 2; mi++)
        #pragma unroll
        for (int ni = 0; ni < 4; ni++)
            #pragma unroll
            for (int j = 0; j < 4; j++) acc[mi][ni][j] = 0.f;

    const int ar = lane & 15, ak = (lane >> 4) * 8;
    const uint32_t a_off = (uint32_t)((warpM * 32 + ar) * KS2 + ak) * 2;
    const int nr = (lane & 7) + ((lane >> 4) * 8);
    const int bk = ((lane >> 3) & 1) * 8;
    const uint32_t b_off = (uint32_t)((warpN * 32 + nr) * KS2 + bk) * 2;

    #pragma unroll
    for (int s = 0; s < STAGES - 1; s++) issue(s, s);

    for (int kt = 0; kt < nk; ++kt) {
        cp_wait<STAGES - 2>();
        __syncthreads();
        if (kt + STAGES - 1 < nk) issue(kt + STAGES - 1, (kt + STAGES - 1) % STAGES);

        const uint32_t st = sbase + (kt % STAGES) * (STAGE_H * 2);
        const uint32_t aA = st + a_off;
        const uint32_t aB = st + OFF_BH * 2 + b_off;

        #pragma unroll
        for (int ks = 0; ks < 2; ks++) {
            const uint32_t ko = ks * 32;
            uint32_t ah_[2][4], al_[2][4], bh_[2][4], bl_[2][4];
            #pragma unroll
            for (int mi = 0; mi < 2; mi++) {
                ldmx4(ah_[mi], aA + mi * (16 * KS2 * 2) + ko);
                ldmx4(al_[mi], aA + OFF_AL * 2 + mi * (16 * KS2 * 2) + ko);
            }
            #pragma unroll
            for (int np = 0; np < 2; np++) {
                ldmx4(bh_[np], aB + np * (16 * KS2 * 2) + ko);
                ldmx4(bl_[np], aB + (OFF_BL - OFF_BH) * 2 + np * (16 * KS2 * 2) + ko);
            }
            #pragma unroll
            for (int mi = 0; mi < 2; mi++)
                #pragma unroll
                for (int ni = 0; ni < 4; ni++) {
                    const int np = ni >> 1, jo = (ni & 1) * 2;
                    mma_bf16(acc[mi][ni], ah_[mi], &bh_[np][jo]);
                    mma_bf16(acc[mi][ni], ah_[mi], &bl_[np][jo]);
                    mma_bf16(acc[mi][ni], al_[mi], &bh_[np][jo]);
                }
        }
    }
    cp_wait<0>();

    // epilogue
    #pragma unroll
    for (int mi = 0; mi < 2; mi++) {
        const int rbase = m0 + warpM * 32 + mi * 16 + gid;
        #pragma unroll
        for (int ni = 0; ni < 4; ni++) {
            const int col = n0 + warpN * 32 + ni * 8 + 2 * tg;
            float* c = acc[mi][ni];
            float b0 = 0.f, b1 = 0.f;
            if (BIAS) { b0 = bias[col]; b1 = bias[col + 1]; }
            #pragma unroll
            for (int h2 = 0; h2 < 2; h2++) {
                const int row = rbase + 8 * h2;
                float v0 = c[2 * h2 + 0] + b0;
                float v1 = c[2 * h2 + 1] + b1;
                if (RELU) { v0 = fmaxf(v0, 0.f); v1 = fmaxf(v1, 0.f); }
                const size_t o = (size_t)bz * sC + (size_t)row * N + col;
                if (WF32)
                    *reinterpret_cast<float2*>(Cf + o) = make_float2(v0, v1);
                if (WSPL || WT) {
                    bf16 h0_, l0_, h1_, l1_;
                    split2(v0, h0_, l0_); split2(v1, h1_, l1_);
                    if (WSPL) {
                        *reinterpret_cast<__nv_bfloat162*>(Ch + o) = __nv_bfloat162(h0_, h1_);
                        *reinterpret_cast<__nv_bfloat162*>(Cl + o) = __nv_bfloat162(l0_, l1_);
                    }
                    if (WT) {
                        // hT layout: [batch][Dd][Nn]; batch = row>>11, n = row&2047
                        const int bb_ = row >> 11, nn_ = row & 2047;
                        const size_t ot = (size_t)bb_ * (Dd * (size_t)Nn)
                                        + (size_t)col * Nn + nn_;
                        Th[ot] = h0_;      Tl[ot] = l0_;
                        Th[ot + Nn] = h1_; Tl[ot + Nn] = l1_;
                    }
                }
            }
        }
    }
}

// ---------------- launch --------------------------------------------------------
extern "C" void kernel_launch(void* const* d_in, const int* in_sizes, int n_in,
                              void* d_out, int out_size)
{
    (void)in_sizes; (void)n_in; (void)out_size;
    const float* x      = (const float*)d_in[0];
    const float* adj    = (const float*)d_in[1];
    const float* W_mlp2 = (const float*)d_in[2];
    const float* b_mlp2 = (const float*)d_in[3];
    const float* Wr[3]  = {(const float*)d_in[4], (const float*)d_in[7], (const float*)d_in[10]};
    const float* Wo[3]  = {(const float*)d_in[5], (const float*)d_in[8], (const float*)d_in[11]};
    const float* bs[3]  = {(const float*)d_in[6], (const float*)d_in[9], (const float*)d_in[12]};
    const float* W_mlp1 = (const float*)d_in[13];
    const float* b_mlp1 = (const float*)d_in[14];
    float* out = (float*)d_out;

    bf16 *h0h, *h0l, *h1h, *h1l, *aggh, *aggl, *hTh, *hTl;
    bf16 *xh, *xl, *W2h, *W2l, *W1h, *W1l, *Wrh, *Wrl, *Woh, *Wol, *adjh, *adjl;
    cudaGetSymbolAddress((void**)&h0h,  g_h0h); cudaGetSymbolAddress((void**)&h0l, g_h0l);
    cudaGetSymbolAddress((void**)&h1h,  g_h1h); cudaGetSymbolAddress((void**)&h1l, g_h1l);
    cudaGetSymbolAddress((void**)&aggh, g_aggh); cudaGetSymbolAddress((void**)&aggl, g_aggl);
    cudaGetSymbolAddress((void**)&hTh,  g_hTh); cudaGetSymbolAddress((void**)&hTl, g_hTl);
    cudaGetSymbolAddress((void**)&xh,   g_xh);  cudaGetSymbolAddress((void**)&xl,  g_xl);
    cudaGetSymbolAddress((void**)&W2h,  g_W2h); cudaGetSymbolAddress((void**)&W2l, g_W2l);
    cudaGetSymbolAddress((void**)&W1h,  g_W1h); cudaGetSymbolAddress((void**)&W1l, g_W1l);
    cudaGetSymbolAddress((void**)&Wrh,  g_Wrh); cudaGetSymbolAddress((void**)&Wrl, g_Wrl);
    cudaGetSymbolAddress((void**)&Woh,  g_Woh); cudaGetSymbolAddress((void**)&Wol, g_Wol);
    cudaGetSymbolAddress((void**)&adjh, g_adjh); cudaGetSymbolAddress((void**)&adjl, g_adjl);

    cudaFuncSetAttribute(gemm_bf<false, false, true,  false, true,  true >,
                         cudaFuncAttributeMaxDynamicSharedMemorySize, GEMM_SMEM);
    cudaFuncSetAttribute(gemm_bf<false, false, false, false, true,  false>,
                         cudaFuncAttributeMaxDynamicSharedMemorySize, GEMM_SMEM);
    cudaFuncSetAttribute(gemm_bf<true,  true,  true,  false, true,  true >,
                         cudaFuncAttributeMaxDynamicSharedMemorySize, GEMM_SMEM);
    cudaFuncSetAttribute(gemm_bf<true,  false, true,  false, true,  false>,
                         cudaFuncAttributeMaxDynamicSharedMemorySize, GEMM_SMEM);
    cudaFuncSetAttribute(gemm_bf<false, false, true,  true,  false, false>,
                         cudaFuncAttributeMaxDynamicSharedMemorySize, GEMM_SMEM);

    const size_t sHD = (size_t)Nn * Dd;

    // preprocessing: 3 launches
    adj_fused<<<Nn, 256>>>(adj);
    x_split_kernel<<<(MT * LD_ / 2) / 256, 256>>>((const float2*)x);
    wtrans_all<<<480, dim3(32, 8)>>>(W_mlp2, W_mlp1, Wr[0], Wo[0], Wr[1], Wo[1], Wr[2], Wo[2]);

    // mlp2: h0 = x @ W_mlp2 + b   (writes split + split-T)
    gemm_bf<false, false, true, false, true, true><<<dim3(1, MT / BM, 1), 256, GEMM_SMEM>>>(
        xh, xl, W2h, W2l, nullptr, nullptr, nullptr, nullptr,
        b_mlp2, nullptr, h0h, h0l, hTh, hTl, Dd, LD_, 0, 0, 0);

    bf16* hinh = h0h; bf16* hinl = h0l;
    bf16* houth = h1h; bf16* houtl = h1l;
    for (int l = 0; l < 3; l++) {
        // agg = adjn @ hin  (per batch; M=2048, N=128, K=2048), B = hT
        gemm_bf<false, false, false, false, true, false><<<dim3(1, Nn / BM, Bb), 256, GEMM_SMEM>>>(
            adjh, adjl, hTh, hTl, nullptr, nullptr, nullptr, nullptr,
            nullptr, nullptr, aggh, aggl, nullptr, nullptr, Dd, Nn, 0, sHD, sHD);
        // h' = act(agg@Wr + hin@Wo + b); layers 0,1 also emit next hT
        if (l < 2)
            gemm_bf<true, true, true, false, true, true><<<dim3(1, MT / BM, 1), 256, GEMM_SMEM>>>(
                aggh, aggl, Wrh + l * Dd * Dd, Wrl + l * Dd * Dd,
                hinh, hinl, Woh + l * Dd * Dd, Wol + l * Dd * Dd,
                bs[l], nullptr, houth, houtl, hTh, hTl, Dd, Dd, 0, 0, 0);
        else
            gemm_bf<true, false, true, false, true, false><<<dim3(1, MT / BM, 1), 256, GEMM_SMEM>>>(
                aggh, aggl, Wrh + l * Dd * Dd, Wrl + l * Dd * Dd,
                hinh, hinl, Woh + l * Dd * Dd, Wol + l * Dd * Dd,
                bs[l], nullptr, houth, houtl, nullptr, nullptr, Dd, Dd, 0, 0, 0);
        { bf16* t = hinh; hinh = houth; houth = t; }
        { bf16* t = hinl; hinl = houtl; houtl = t; }
    }

    // mlp1: out = hin @ W_mlp1 + b   (M=8192, N=1536, K=128)
    gemm_bf<false, false, true, true, false, false><<<dim3(LD_ / BN, MT / BM, 1), 256, GEMM_SMEM>>>(
        hinh, hinl, W1h, W1l, nullptr, nullptr, nullptr, nullptr,
        b_mlp1, out, nullptr, nullptr, nullptr, nullptr, LD_, Dd, 0, 0, 0);
}